// round 1
// baseline (speedup 1.0000x reference)
#include <cuda_runtime.h>
#include <math.h>
#include <stdint.h>

#define BATCH 128
#define NPTS  1024
#define DIM   128

// 512 MB scratch for squared-distance matrices, per-sample row-major [b][i][j].
__device__ float g_D[(size_t)BATCH * NPTS * NPTS];
__device__ float g_norm[BATCH * NPTS];
__device__ float g_partial[BATCH];

// ---------------------------------------------------------------------------
// Kernel 1: squared row norms. One warp per point (row of 128 floats).
// ---------------------------------------------------------------------------
__global__ void norms_kernel(const float* __restrict__ X) {
    int warp = (blockIdx.x * blockDim.x + threadIdx.x) >> 5;
    int lane = threadIdx.x & 31;
    if (warp >= BATCH * NPTS) return;
    const float4* row = (const float4*)(X + (size_t)warp * DIM);
    float4 v = row[lane];                       // 32 lanes x 4 floats = 128
    float s = v.x * v.x + v.y * v.y + v.z * v.z + v.w * v.w;
    #pragma unroll
    for (int o = 16; o; o >>= 1) s += __shfl_down_sync(0xffffffffu, s, o);
    if (lane == 0) g_norm[warp] = s;
}

// ---------------------------------------------------------------------------
// Kernel 2: batched Gram -> squared distances.
// Tile 64x64 output, K staged in chunks of 64. Block 16x16; each thread does
// a 4x4 micro-tile at (ty+16m, tx+16n) so global stores are coalesced and
// the 65-float smem row pad makes both operand reads conflict-free.
// ---------------------------------------------------------------------------
__global__ void dist_kernel(const float* __restrict__ X) {
    __shared__ float As[64][65];
    __shared__ float Bs[64][65];

    const int b  = blockIdx.z;
    const int I  = blockIdx.y * 64;
    const int J  = blockIdx.x * 64;
    const int tx = threadIdx.x;       // 0..15
    const int ty = threadIdx.y;       // 0..15
    const int tid = ty * 16 + tx;

    const float* Xb = X + (size_t)b * NPTS * DIM;

    float acc[4][4];
    #pragma unroll
    for (int m = 0; m < 4; ++m)
        #pragma unroll
        for (int n = 0; n < 4; ++n) acc[m][n] = 0.f;

    for (int k0 = 0; k0 < DIM; k0 += 64) {
        __syncthreads();
        // stage 64 rows x 64 k-cols of each operand; coalesced loads,
        // conflict-free stores (consecutive c -> consecutive banks).
        #pragma unroll
        for (int e = tid; e < 64 * 64; e += 256) {
            int r = e >> 6, c = e & 63;
            As[r][c] = Xb[(size_t)(I + r) * DIM + k0 + c];
            Bs[r][c] = Xb[(size_t)(J + r) * DIM + k0 + c];
        }
        __syncthreads();

        #pragma unroll 16
        for (int kk = 0; kk < 64; ++kk) {
            float a0 = As[ty     ][kk];
            float a1 = As[ty + 16][kk];
            float a2 = As[ty + 32][kk];
            float a3 = As[ty + 48][kk];
            float b0 = Bs[tx     ][kk];
            float b1 = Bs[tx + 16][kk];
            float b2 = Bs[tx + 32][kk];
            float b3 = Bs[tx + 48][kk];
            acc[0][0] += a0 * b0; acc[0][1] += a0 * b1; acc[0][2] += a0 * b2; acc[0][3] += a0 * b3;
            acc[1][0] += a1 * b0; acc[1][1] += a1 * b1; acc[1][2] += a1 * b2; acc[1][3] += a1 * b3;
            acc[2][0] += a2 * b0; acc[2][1] += a2 * b1; acc[2][2] += a2 * b2; acc[2][3] += a2 * b3;
            acc[3][0] += a3 * b0; acc[3][1] += a3 * b1; acc[3][2] += a3 * b2; acc[3][3] += a3 * b3;
        }
    }

    // D^2 = |xi|^2 + |xj|^2 - 2 xi.xj  (clamped at 0 for rounding)
    float ni[4], nj[4];
    #pragma unroll
    for (int m = 0; m < 4; ++m) ni[m] = g_norm[b * NPTS + I + ty + 16 * m];
    #pragma unroll
    for (int n = 0; n < 4; ++n) nj[n] = g_norm[b * NPTS + J + tx + 16 * n];

    float* Db = g_D + ((size_t)b << 20);
    #pragma unroll
    for (int m = 0; m < 4; ++m) {
        int row = I + ty + 16 * m;
        float* Drow = Db + (size_t)row * NPTS + J + tx;
        #pragma unroll
        for (int n = 0; n < 4; ++n) {
            Drow[16 * n] = fmaxf(ni[m] + nj[n] - 2.f * acc[m][n], 0.f);
        }
    }
}

// ---------------------------------------------------------------------------
// Kernel 3: Prim's MST per sample. One CTA of 1024 threads per sample;
// thread t owns point t (mindist in a register). Argmin on squared distances
// (monotone), sqrt only on the selected death. Ties break to lower index to
// match jnp.argmin.
// ---------------------------------------------------------------------------
__global__ void prim_kernel() {
    const int b   = blockIdx.x;
    const int tid = threadIdx.x;
    const int lane = tid & 31;
    const int wid  = tid >> 5;

    const float* Db = g_D + ((size_t)b << 20);

    const float INF = 3.4e38f;
    float mind   = Db[tid];             // distances^2 to point 0
    bool visited = (tid == 0);

    __shared__ float s_val[32];
    __shared__ int   s_idx[32];
    __shared__ float s_death;
    __shared__ int   s_j;

    float total = 0.f;

    for (int it = 0; it < NPTS - 1; ++it) {
        float v  = visited ? INF : mind;
        int   idx = tid;
        // warp argmin with lowest-index tie-break
        #pragma unroll
        for (int o = 16; o; o >>= 1) {
            float ov = __shfl_down_sync(0xffffffffu, v, o);
            int   oi = __shfl_down_sync(0xffffffffu, idx, o);
            if (ov < v || (ov == v && oi < idx)) { v = ov; idx = oi; }
        }
        if (lane == 0) { s_val[wid] = v; s_idx[wid] = idx; }
        __syncthreads();
        if (wid == 0) {
            v   = s_val[lane];
            idx = s_idx[lane];
            #pragma unroll
            for (int o = 16; o; o >>= 1) {
                float ov = __shfl_down_sync(0xffffffffu, v, o);
                int   oi = __shfl_down_sync(0xffffffffu, idx, o);
                if (ov < v || (ov == v && oi < idx)) { v = ov; idx = oi; }
            }
            if (lane == 0) { s_j = idx; s_death = v; }
        }
        __syncthreads();
        int j = s_j;
        if (tid == 0) total += sqrtf(s_death);
        float dj = Db[(size_t)j * NPTS + tid];     // coalesced row gather
        if (tid == j) visited = true;
        if (!visited) mind = fminf(mind, dj);
    }
    if (tid == 0) g_partial[b] = total;            // sum of MST edge lengths
}

// ---------------------------------------------------------------------------
// Kernel 4: final scalar. loss = (sum_b sum_of_deaths_b) / (1023 * 128 * 2)
// ---------------------------------------------------------------------------
__global__ void final_kernel(float* __restrict__ out) {
    const int t = threadIdx.x;       // 128 threads
    const int lane = t & 31, wid = t >> 5;
    __shared__ float s[4];
    float v = g_partial[t];
    #pragma unroll
    for (int o = 16; o; o >>= 1) v += __shfl_down_sync(0xffffffffu, v, o);
    if (lane == 0) s[wid] = v;
    __syncthreads();
    if (t == 0) {
        float sum = s[0] + s[1] + s[2] + s[3];
        out[0] = sum / (1023.f * (float)BATCH * 2.f);
    }
}

// ---------------------------------------------------------------------------
extern "C" void kernel_launch(void* const* d_in, const int* in_sizes, int n_in,
                              void* d_out, int out_size) {
    (void)in_sizes; (void)n_in; (void)out_size;
    const float* X = (const float*)d_in[0];
    float* out = (float*)d_out;

    // 131072 rows, one warp each, 8 warps/block
    norms_kernel<<<16384, 256>>>(X);
    dist_kernel<<<dim3(16, 16, BATCH), dim3(16, 16)>>>(X);
    prim_kernel<<<BATCH, NPTS>>>();
    final_kernel<<<1, 128>>>(out);
}

// round 4
// speedup vs baseline: 2.1265x; 2.1265x over previous
#include <cuda_runtime.h>
#include <cuda_bf16.h>
#include <math.h>
#include <stdint.h>

#define BATCH 128
#define NPTS  1024
#define DIM   128

// Scratch (device globals: allocation-free).
__device__ float          g_D[(size_t)BATCH * NPTS * NPTS];   // 512 MB dist^2
__device__ __nv_bfloat16  g_Xb[(size_t)BATCH * NPTS * DIM];   // 32 MB bf16 copy
__device__ float          g_norm[BATCH * NPTS];
__device__ float          g_partial[BATCH];

// ---------------------------------------------------------------------------
// Kernel 1: squared row norms (fp32, exact). One warp per point.
// ---------------------------------------------------------------------------
__global__ void norms_kernel(const float* __restrict__ X) {
    int warp = (blockIdx.x * blockDim.x + threadIdx.x) >> 5;
    int lane = threadIdx.x & 31;
    if (warp >= BATCH * NPTS) return;
    const float4* row = (const float4*)(X + (size_t)warp * DIM);
    float4 v = row[lane];
    float s = v.x * v.x + v.y * v.y + v.z * v.z + v.w * v.w;
    #pragma unroll
    for (int o = 16; o; o >>= 1) s += __shfl_down_sync(0xffffffffu, s, o);
    if (lane == 0) g_norm[warp] = s;
}

// ---------------------------------------------------------------------------
// Kernel 2: fp32 -> bf16 conversion of X.
// ---------------------------------------------------------------------------
__global__ void convert_kernel(const float* __restrict__ X) {
    size_t i = ((size_t)blockIdx.x * blockDim.x + threadIdx.x) * 4;
    float4 v = *(const float4*)(X + i);
    __nv_bfloat162* dst = (__nv_bfloat162*)(g_Xb + i);
    dst[0] = __floats2bfloat162_rn(v.x, v.y);
    dst[1] = __floats2bfloat162_rn(v.z, v.w);
}

// ---------------------------------------------------------------------------
// Kernel 3: batched Gram via bf16 mma.sync (m16n8k16), D^2 epilogue in fp32.
// CTA computes a 128x128 tile of one sample. 8 warps in a 4(m) x 2(n) grid:
// each warp 32 rows x 64 cols = 2 m-tiles x 8 n-tiles. K staged in 2 chunks
// of 64; smem rows padded to 72 bf16 for conflict-free fragment LDS.
// ---------------------------------------------------------------------------
#define KCH   64
#define LDR   72   // padded row length in bf16

__device__ __forceinline__ void mma16816(float* c, const uint32_t* a,
                                         uint32_t b0, uint32_t b1) {
    asm volatile(
        "mma.sync.aligned.m16n8k16.row.col.f32.bf16.bf16.f32 "
        "{%0,%1,%2,%3}, {%4,%5,%6,%7}, {%8,%9}, {%0,%1,%2,%3};\n"
        : "+f"(c[0]), "+f"(c[1]), "+f"(c[2]), "+f"(c[3])
        : "r"(a[0]), "r"(a[1]), "r"(a[2]), "r"(a[3]), "r"(b0), "r"(b1));
}

__global__ __launch_bounds__(256, 1)
void dist_kernel() {
    __shared__ __align__(16) __nv_bfloat16 As[128 * LDR];
    __shared__ __align__(16) __nv_bfloat16 Bs[128 * LDR];

    const int b  = blockIdx.z;
    const int I  = blockIdx.y * 128;
    const int J  = blockIdx.x * 128;
    const int tid  = threadIdx.x;
    const int lane = tid & 31;
    const int wid  = tid >> 5;
    const int wm   = wid & 3;     // 0..3 -> row block of 32
    const int wn   = wid >> 2;    // 0..1 -> col block of 64

    const __nv_bfloat16* Xb = g_Xb + (size_t)b * NPTS * DIM;

    float acc[2][8][4];
    #pragma unroll
    for (int m = 0; m < 2; ++m)
        #pragma unroll
        for (int n = 0; n < 8; ++n)
            #pragma unroll
            for (int q = 0; q < 4; ++q) acc[m][n][q] = 0.f;

    const uint32_t* As32 = (const uint32_t*)As;
    const uint32_t* Bs32 = (const uint32_t*)Bs;

    for (int k0 = 0; k0 < DIM; k0 += KCH) {
        __syncthreads();
        // stage 128 rows x 64 k of both operands (16B vector loads/stores)
        #pragma unroll
        for (int i = 0; i < 4; ++i) {
            int e  = tid + 256 * i;          // 0..1023
            int r  = e >> 3;
            int c8 = e & 7;                  // 8 bf16 chunk
            uint4 va = *(const uint4*)(Xb + (size_t)(I + r) * DIM + k0 + c8 * 8);
            uint4 vb = *(const uint4*)(Xb + (size_t)(J + r) * DIM + k0 + c8 * 8);
            *(uint4*)(As + r * LDR + c8 * 8) = va;
            *(uint4*)(Bs + r * LDR + c8 * 8) = vb;
        }
        __syncthreads();

        #pragma unroll
        for (int ks = 0; ks < KCH / 16; ++ks) {
            const int c = ks * 16 + (lane & 3) * 2;   // bf16 col of this lane
            // A fragments for both m-tiles
            uint32_t a[2][4];
            #pragma unroll
            for (int mt = 0; mt < 2; ++mt) {
                int r0 = wm * 32 + mt * 16 + (lane >> 2);
                a[mt][0] = As32[(r0 * LDR + c) >> 1];
                a[mt][1] = As32[((r0 + 8) * LDR + c) >> 1];
                a[mt][2] = As32[(r0 * LDR + c + 8) >> 1];
                a[mt][3] = As32[((r0 + 8) * LDR + c + 8) >> 1];
            }
            #pragma unroll
            for (int nt = 0; nt < 8; ++nt) {
                int jr = wn * 64 + nt * 8 + (lane >> 2);
                uint32_t b0 = Bs32[(jr * LDR + c) >> 1];
                uint32_t b1 = Bs32[(jr * LDR + c + 8) >> 1];
                mma16816(acc[0][nt], a[0], b0, b1);
                mma16816(acc[1][nt], a[1], b0, b1);
            }
        }
    }

    // Epilogue: D^2 = max(ni + nj - 2*dot, 0)
    float* Db = g_D + ((size_t)b << 20);
    const float* nb = g_norm + b * NPTS;
    #pragma unroll
    for (int mt = 0; mt < 2; ++mt) {
        int r0 = I + wm * 32 + mt * 16 + (lane >> 2);
        float ni0 = nb[r0], ni1 = nb[r0 + 8];
        #pragma unroll
        for (int nt = 0; nt < 8; ++nt) {
            int col = J + wn * 64 + nt * 8 + (lane & 3) * 2;
            float nj0 = nb[col], nj1 = nb[col + 1];
            float2 v0, v1;
            v0.x = fmaxf(ni0 + nj0 - 2.f * acc[mt][nt][0], 0.f);
            v0.y = fmaxf(ni0 + nj1 - 2.f * acc[mt][nt][1], 0.f);
            v1.x = fmaxf(ni1 + nj0 - 2.f * acc[mt][nt][2], 0.f);
            v1.y = fmaxf(ni1 + nj1 - 2.f * acc[mt][nt][3], 0.f);
            *(float2*)(Db + (size_t)r0 * NPTS + col)       = v0;
            *(float2*)(Db + (size_t)(r0 + 8) * NPTS + col) = v1;
        }
    }
}

// ---------------------------------------------------------------------------
// Kernel 4: Prim's MST. 256 threads/CTA, each owns 4 points in registers.
// Argmin via packed u32 key = round22(dist^2 bits) | idx10, one REDUX per
// warp + one-warp stage 2.
// Visited is encoded as mind = -INF: it is STICKY under fminf (unlike +INF,
// which would be overwritten by the very next min-update — that was the R3
// bug), and its bit pattern 0xFF800000 packs to a key larger than any
// positive-float key, so visited points can never win the argmin.
// ---------------------------------------------------------------------------
__global__ __launch_bounds__(256, 1)
void prim_kernel() {
    const int b    = blockIdx.x;
    const int tid  = threadIdx.x;
    const int lane = tid & 31;
    const int wid  = tid >> 5;

    const float* Db = g_D + ((size_t)b << 20);
    const float NEG_INF = __int_as_float(0xff800000);

    float mind[4];
    #pragma unroll
    for (int i = 0; i < 4; ++i) {
        int pt = tid + 256 * i;
        mind[i] = (pt == 0) ? NEG_INF : Db[pt];  // row 0 = dists^2 to start
    }

    __shared__ uint32_t s_warp[8];
    __shared__ uint32_t s_best;

    float total = 0.f;

    for (int it = 0; it < NPTS - 1; ++it) {
        // pack keys: high 22 bits of rounded dist^2, low 10 bits = point id
        uint32_t kmin = 0xFFFFFFFFu;
        #pragma unroll
        for (int i = 0; i < 4; ++i) {
            uint32_t fb = __float_as_uint(mind[i]);
            uint32_t k  = ((fb + 0x200u) & 0xFFFFFC00u) | (uint32_t)(tid + 256 * i);
            kmin = min(kmin, k);
        }
        kmin = __reduce_min_sync(0xffffffffu, kmin);
        if (lane == 0) s_warp[wid] = kmin;
        __syncthreads();
        if (wid == 0) {
            uint32_t v = (lane < 8) ? s_warp[lane] : 0xFFFFFFFFu;
            v = __reduce_min_sync(0xffffffffu, v);
            if (lane == 0) s_best = v;
        }
        __syncthreads();
        uint32_t best = s_best;
        int j = (int)(best & 1023u);
        if (tid == 0) total += sqrtf(__uint_as_float(best & 0xFFFFFC00u));

        const float* row = Db + ((size_t)j << 10);
        #pragma unroll
        for (int i = 0; i < 4; ++i) {
            int pt = tid + 256 * i;
            float dj = row[pt];
            mind[i] = (pt == j) ? NEG_INF : fminf(mind[i], dj);
        }
        __syncthreads();   // protect s_best before next iteration's write
    }
    if (tid == 0) g_partial[b] = total;
}

// ---------------------------------------------------------------------------
// Kernel 5: final scalar.
// ---------------------------------------------------------------------------
__global__ void final_kernel(float* __restrict__ out) {
    const int t = threadIdx.x;           // 128 threads
    const int lane = t & 31, wid = t >> 5;
    __shared__ float s[4];
    float v = g_partial[t];
    #pragma unroll
    for (int o = 16; o; o >>= 1) v += __shfl_down_sync(0xffffffffu, v, o);
    if (lane == 0) s[wid] = v;
    __syncthreads();
    if (t == 0) out[0] = (s[0] + s[1] + s[2] + s[3]) / (1023.f * (float)BATCH * 2.f);
}

// ---------------------------------------------------------------------------
extern "C" void kernel_launch(void* const* d_in, const int* in_sizes, int n_in,
                              void* d_out, int out_size) {
    (void)in_sizes; (void)n_in; (void)out_size;
    const float* X = (const float*)d_in[0];
    float* out = (float*)d_out;

    norms_kernel<<<16384, 256>>>(X);                 // 131072 warps
    convert_kernel<<<16384, 256>>>(X);               // 16.8M elems / 4 per thread
    dist_kernel<<<dim3(8, 8, BATCH), 256>>>();
    prim_kernel<<<BATCH, 256>>>();
    final_kernel<<<1, 128>>>(out);
}